// round 1
// baseline (speedup 1.0000x reference)
#include <cuda_runtime.h>
#include <math.h>

// maps: [128, 33, 224, 224] fp32  -> d_in[0]
// w1:   [100, 33]            fp32 -> d_in[1]
// w2:   [10, 100]            fp32 -> d_in[2]
// out:  x_sun [128,33] (4224 floats) then x_son stack [9,128,10] (11520 floats)

#define PLANE_ELEMS  (224 * 224)       // 50176
#define PLANE_VEC4   (PLANE_ELEMS / 4) // 12544
#define POOL_THREADS 256
#define POOL_ITERS   (PLANE_VEC4 / POOL_THREADS) // 49, exact
#define N_PLANES     (128 * 33)        // 4224
#define BATCH        128
#define X_SUN_ELEMS  (BATCH * 33)      // 4224

// ---------------------------------------------------------------------------
// Kernel 1: global average pool per (b, c) plane. One block per plane.
// ---------------------------------------------------------------------------
__global__ __launch_bounds__(POOL_THREADS, 8)
void pool_kernel(const float4* __restrict__ maps, float* __restrict__ out)
{
    const int plane = blockIdx.x;
    const float4* p = maps + (size_t)plane * PLANE_VEC4;
    const int tid = threadIdx.x;

    float s = 0.0f;
#pragma unroll
    for (int i = 0; i < POOL_ITERS; i++) {
        float4 v = p[tid + i * POOL_THREADS];
        s += (v.x + v.y) + (v.z + v.w);
    }

    // warp reduce
#pragma unroll
    for (int off = 16; off > 0; off >>= 1)
        s += __shfl_down_sync(0xFFFFFFFFu, s, off);

    __shared__ float warp_sums[POOL_THREADS / 32];
    const int lane = tid & 31;
    const int wid  = tid >> 5;
    if (lane == 0) warp_sums[wid] = s;
    __syncthreads();

    if (wid == 0) {
        float t = (lane < POOL_THREADS / 32) ? warp_sums[lane] : 0.0f;
#pragma unroll
        for (int off = 4; off > 0; off >>= 1)
            t += __shfl_down_sync(0xFFFFFFFFu, t, off);
        if (lane == 0)
            out[plane] = t * (1.0f / (float)PLANE_ELEMS);
    }
}

// ---------------------------------------------------------------------------
// Kernel 2: MLP head + top-k vote aggregation. One block per batch element.
// ---------------------------------------------------------------------------
__global__ __launch_bounds__(128, 1)
void head_kernel(const float* __restrict__ w1,
                 const float* __restrict__ w2,
                 float* __restrict__ out)
{
    const int b   = blockIdx.x;
    const int tid = threadIdx.x;

    __shared__ float t33[33];
    __shared__ float g[100];

    // tanh of the pooled means (x_sun lives at out[0:4224])
    if (tid < 33)
        t33[tid] = tanhf(out[b * 33 + tid]);
    __syncthreads();

    // fc1: g[j] = relu( sum_c t33[c] * w1[j, c] )
    if (tid < 100) {
        float s = 0.0f;
#pragma unroll
        for (int c = 0; c < 33; c++)
            s = fmaf(t33[c], w1[tid * 33 + c], s);
        g[tid] = fmaxf(s, 0.0f);
    }
    __syncthreads();

    // per-output: votes, streaming top-20 selection, cumsum, dense sum
    if (tid < 10) {
        const int o = tid;
        float top[20];
#pragma unroll
        for (int i = 0; i < 20; i++) top[i] = -INFINITY;

        float dense = 0.0f;
        for (int i = 0; i < 100; i++) {
            float v = g[i] * w2[o * 100 + i];
            dense += v;
            if (v > top[19]) {
                int j = 19;
                while (j > 0 && top[j - 1] < v) {
                    top[j] = top[j - 1];
                    j--;
                }
                top[j] = v;
            }
        }

        float csum[20];
        float acc = 0.0f;
#pragma unroll
        for (int i = 0; i < 20; i++) {
            acc += top[i];
            csum[i] = acc;
        }

        const int KS[8] = {3, 4, 5, 6, 7, 10, 15, 20};
        float* son = out + X_SUN_ELEMS;
#pragma unroll
        for (int k = 0; k < 8; k++)
            son[k * (BATCH * 10) + b * 10 + o] = csum[KS[k] - 1];
        son[8 * (BATCH * 10) + b * 10 + o] = dense;
    }
}

// ---------------------------------------------------------------------------
extern "C" void kernel_launch(void* const* d_in, const int* in_sizes, int n_in,
                              void* d_out, int out_size)
{
    const float4* maps = (const float4*)d_in[0];
    const float*  w1   = (const float*)d_in[1];
    const float*  w2   = (const float*)d_in[2];
    float* out = (float*)d_out;

    pool_kernel<<<N_PLANES, POOL_THREADS>>>(maps, out);
    head_kernel<<<BATCH, 128>>>(w1, w2, out);
}

// round 2
// speedup vs baseline: 1.1262x; 1.1262x over previous
#include <cuda_runtime.h>
#include <math.h>

// maps: [128, 33, 224, 224] fp32  -> d_in[0]
// w1:   [100, 33]            fp32 -> d_in[1]
// w2:   [10, 100]            fp32 -> d_in[2]
// out:  x_sun [128,33] (4224 floats) then x_son stack [9,128,10] (11520 floats)

#define PLANE_ELEMS  (224 * 224)       // 50176
#define PLANE_VEC4   (PLANE_ELEMS / 4) // 12544
#define POOL_THREADS 256
#define POOL_ITERS   (PLANE_VEC4 / POOL_THREADS) // 49, exact
#define N_PLANES     (128 * 33)        // 4224
#define BATCH        128
#define X_SUN_ELEMS  (BATCH * 33)      // 4224

// ---------------------------------------------------------------------------
// Kernel 1: global average pool per (b, c) plane. One block per plane.
// (at HBM roofline: 848 MB in ~116us = 7.3 TB/s)
// ---------------------------------------------------------------------------
__global__ __launch_bounds__(POOL_THREADS, 8)
void pool_kernel(const float4* __restrict__ maps, float* __restrict__ out)
{
    const int plane = blockIdx.x;
    const float4* p = maps + (size_t)plane * PLANE_VEC4;
    const int tid = threadIdx.x;

    float s = 0.0f;
#pragma unroll
    for (int i = 0; i < POOL_ITERS; i++) {
        float4 v = p[tid + i * POOL_THREADS];
        s += (v.x + v.y) + (v.z + v.w);
    }

#pragma unroll
    for (int off = 16; off > 0; off >>= 1)
        s += __shfl_down_sync(0xFFFFFFFFu, s, off);

    __shared__ float warp_sums[POOL_THREADS / 32];
    const int lane = tid & 31;
    const int wid  = tid >> 5;
    if (lane == 0) warp_sums[wid] = s;
    __syncthreads();

    if (wid == 0) {
        float t = (lane < POOL_THREADS / 32) ? warp_sums[lane] : 0.0f;
#pragma unroll
        for (int off = 4; off > 0; off >>= 1)
            t += __shfl_down_sync(0xFFFFFFFFu, t, off);
        if (lane == 0)
            out[plane] = t * (1.0f / (float)PLANE_ELEMS);
    }
}

// ---------------------------------------------------------------------------
// Kernel 2: MLP head. One block per batch (320 threads = 10 warps).
// Warp w computes output o=w via rank-by-counting top-k selection.
// ---------------------------------------------------------------------------
__global__ __launch_bounds__(320, 4)
void head_kernel(const float* __restrict__ w1,
                 const float* __restrict__ w2,
                 float* __restrict__ out)
{
    const int b    = blockIdx.x;
    const int tid  = threadIdx.x;
    const int lane = tid & 31;
    const int wrp  = tid >> 5;      // 0..9 = output index o

    __shared__ float t33[33];
    __shared__ float g[100];
    __shared__ float votes[10][104]; // padded rows

    // tanh of pooled means (x_sun already written at out[0:4224])
    if (tid < 33)
        t33[tid] = tanhf(out[b * 33 + tid]);
    __syncthreads();

    // fc1 + relu
    if (tid < 100) {
        float s = 0.0f;
#pragma unroll
        for (int c = 0; c < 33; c++)
            s = fmaf(t33[c], w1[tid * 33 + c], s);
        g[tid] = fmaxf(s, 0.0f);
    }
    __syncthreads();

    // ---- per-warp: votes for output o = wrp ----
    const int o = wrp;
    float v0 = g[lane]      * w2[o * 100 + lane];
    float v1 = g[lane + 32] * w2[o * 100 + lane + 32];
    float v2 = g[lane + 64] * w2[o * 100 + lane + 64];
    float v3 = (lane < 4) ? g[lane + 96] * w2[o * 100 + lane + 96] : 0.0f;

    votes[o][lane]      = v0;
    votes[o][lane + 32] = v1;
    votes[o][lane + 64] = v2;
    if (lane < 4) votes[o][lane + 96] = v3;
    __syncwarp();

    // rank of each owned value: # of values strictly greater (index tie-break)
    int r0 = 0, r1 = 0, r2 = 0, r3 = 0;
    const int i0 = lane, i1 = lane + 32, i2 = lane + 64, i3 = lane + 96;
#pragma unroll 4
    for (int j = 0; j < 100; j++) {
        float u = votes[o][j];                 // broadcast read
        r0 += (u > v0) | ((u == v0) & (j < i0));
        r1 += (u > v1) | ((u == v1) & (j < i1));
        r2 += (u > v2) | ((u == v2) & (j < i2));
        r3 += (u > v3) | ((u == v3) & (j < i3));
    }
    if (lane >= 4) r3 = 100;                   // invalidate non-existent value

    // partial top-k sums: value with rank r contributes to every k > r
    const int KS[8] = {3, 4, 5, 6, 7, 10, 15, 20};
    float sk[9];
#pragma unroll
    for (int k = 0; k < 8; k++) {
        float a = 0.0f;
        if (r0 < KS[k]) a += v0;
        if (r1 < KS[k]) a += v1;
        if (r2 < KS[k]) a += v2;
        if (r3 < KS[k]) a += v3;
        sk[k] = a;
    }
    sk[8] = v0 + v1 + v2 + v3;                 // dense pass

    // warp reduce the 9 partials
#pragma unroll
    for (int k = 0; k < 9; k++) {
#pragma unroll
        for (int off = 16; off > 0; off >>= 1)
            sk[k] += __shfl_down_sync(0xFFFFFFFFu, sk[k], off);
    }

    if (lane == 0) {
        float* son = out + X_SUN_ELEMS;
#pragma unroll
        for (int k = 0; k < 9; k++)
            son[k * (BATCH * 10) + b * 10 + o] = sk[k];
    }
}

// ---------------------------------------------------------------------------
extern "C" void kernel_launch(void* const* d_in, const int* in_sizes, int n_in,
                              void* d_out, int out_size)
{
    const float4* maps = (const float4*)d_in[0];
    const float*  w1   = (const float*)d_in[1];
    const float*  w2   = (const float*)d_in[2];
    float* out = (float*)d_out;

    pool_kernel<<<N_PLANES, POOL_THREADS>>>(maps, out);
    head_kernel<<<BATCH, 320>>>(w1, w2, out);
}